// round 1
// baseline (speedup 1.0000x reference)
#include <cuda_runtime.h>
#include <cuda_bf16.h>

#define DD 64
#define NMAX 100000
#define EMAX 1600000
#define GMAX 1024
#define NB_SCAN 240

// -------- scratch (static device globals; no allocation) --------
__device__ float g_h0[NMAX * DD];
__device__ float g_h1[NMAX * DD];
__device__ float g_t [NMAX * DD];
__device__ int   g_deg[NMAX];
__device__ int   g_offs[NMAX + 1];
__device__ int   g_cursor[NMAX];
__device__ int   g_srcs[EMAX];
__device__ float g_invdeg[NMAX];
__device__ float g_pool[GMAX * DD];
__device__ float g_cnt[GMAX];
__device__ int   g_bsum[NB_SCAN];
__device__ int   g_boff[NB_SCAN];

// -------- init: zero deg / pool / cnt --------
__global__ void k_zero(int n, int g) {
    int i = blockIdx.x * blockDim.x + threadIdx.x;
    int total = n;
    for (int idx = i; idx < total; idx += gridDim.x * blockDim.x) {
        g_deg[idx] = 0;
        if (idx < g * DD) g_pool[idx] = 0.f;
        if (idx < g)      g_cnt[idx]  = 0.f;
    }
}

// -------- degree count --------
__global__ void k_deg(const int* __restrict__ dst, int e) {
    int i = blockIdx.x * blockDim.x + threadIdx.x;
    if (i < e) atomicAdd(&g_deg[dst[i]], 1);
}

__global__ void k_invdeg(int n) {
    int i = blockIdx.x * blockDim.x + threadIdx.x;
    if (i < n) {
        int d = g_deg[i];
        g_invdeg[i] = 1.0f / (float)(d > 0 ? d : 1);
    }
}

// -------- 3-phase exclusive scan of g_deg -> g_offs (+cursor copy) --------
__global__ void k_scan_a(int n) {
    __shared__ int s[256];
    int b = blockIdx.x;
    int ch = (n + NB_SCAN - 1) / NB_SCAN;
    int lo = b * ch, hi = min(n, lo + ch);
    int t = threadIdx.x;
    int acc = 0;
    for (int i = lo + t; i < hi; i += 256) acc += g_deg[i];
    s[t] = acc;
    __syncthreads();
    for (int off = 128; off > 0; off >>= 1) {
        if (t < off) s[t] += s[t + off];
        __syncthreads();
    }
    if (t == 0) g_bsum[b] = s[0];
}

__global__ void k_scan_b() {
    // single thread sequential scan over 240 block sums
    if (threadIdx.x == 0 && blockIdx.x == 0) {
        int run = 0;
        for (int i = 0; i < NB_SCAN; ++i) { g_boff[i] = run; run += g_bsum[i]; }
    }
}

__global__ void k_scan_c(int n, int e) {
    __shared__ int s[256];
    int b = blockIdx.x;
    int t = threadIdx.x;
    if (b == 0 && t == 0) g_offs[n] = e;
    int ch = (n + NB_SCAN - 1) / NB_SCAN;
    int lo = b * ch, hi = min(n, lo + ch);
    int carry = g_boff[b];
    for (int base = lo; base < hi; base += 256) {
        int idx = base + t;
        int v = (idx < hi) ? g_deg[idx] : 0;
        s[t] = v;
        __syncthreads();
        // Hillis-Steele inclusive scan
        for (int off = 1; off < 256; off <<= 1) {
            int x = (t >= off) ? s[t - off] : 0;
            __syncthreads();
            s[t] += x;
            __syncthreads();
        }
        if (idx < hi) {
            int exc = carry + s[t] - v;
            g_offs[idx]   = exc;
            g_cursor[idx] = exc;
        }
        carry += s[255];
        __syncthreads();
    }
}

// -------- scatter edges into CSR --------
__global__ void k_scatter(const int* __restrict__ src, const int* __restrict__ dst, int e) {
    int i = blockIdx.x * blockDim.x + threadIdx.x;
    if (i < e) {
        int p = atomicAdd(&g_cursor[dst[i]], 1);
        g_srcs[p] = src[i];
    }
}

// -------- embedding gather --------
__global__ void k_embed(const int* __restrict__ tokens, const float* __restrict__ emb, int n) {
    int i = blockIdx.x * blockDim.x + threadIdx.x;  // one float4 per thread
    int total = n * (DD / 4);
    if (i < total) {
        int node = i >> 4;         // DD/4 = 16
        int q    = i & 15;
        int tok = tokens[node];
        ((float4*)g_h0)[node * 16 + q] = ((const float4*)emb)[tok * 16 + q];
    }
}

// -------- GEMM: t = hin @ W   (64-row tiles, 2x8 register blocking) --------
__global__ void k_gemm(const float* __restrict__ hin, const float* __restrict__ W,
                       float* __restrict__ tout, int n) {
    __shared__ float sA[64 * 68];
    __shared__ float sW[64 * 68];
    int t = threadIdx.x;
    int row0 = blockIdx.x * 64;

    // load 64x64 A tile + full 64x64 W into padded smem
    #pragma unroll
    for (int it = 0; it < 4; ++it) {
        int flat = t + it * 256;        // float4 index within 64x16(float4)
        int r  = flat >> 4;
        int c4 = flat & 15;
        float4 v = make_float4(0.f, 0.f, 0.f, 0.f);
        int gr = row0 + r;
        if (gr < n) v = ((const float4*)hin)[gr * 16 + c4];
        *(float4*)&sA[r * 68 + c4 * 4] = v;
        float4 w = ((const float4*)W)[flat];
        *(float4*)&sW[r * 68 + c4 * 4] = w;
    }
    __syncthreads();

    int tx = t & 7;          // 8 col groups
    int ty = t >> 3;         // 32 row groups
    int r0 = ty * 2;
    float acc[2][8];
    #pragma unroll
    for (int i = 0; i < 2; ++i)
        #pragma unroll
        for (int j = 0; j < 8; ++j) acc[i][j] = 0.f;

    #pragma unroll
    for (int k4 = 0; k4 < 64; k4 += 4) {
        float4 a0 = *(const float4*)&sA[(r0 + 0) * 68 + k4];
        float4 a1 = *(const float4*)&sA[(r0 + 1) * 68 + k4];
        #pragma unroll
        for (int kk = 0; kk < 4; ++kk) {
            int k = k4 + kk;
            float4 w0 = *(const float4*)&sW[k * 68 + tx * 8];
            float4 w1 = *(const float4*)&sW[k * 68 + tx * 8 + 4];
            float a0k = (&a0.x)[kk];
            float a1k = (&a1.x)[kk];
            acc[0][0] += a0k * w0.x; acc[0][1] += a0k * w0.y;
            acc[0][2] += a0k * w0.z; acc[0][3] += a0k * w0.w;
            acc[0][4] += a0k * w1.x; acc[0][5] += a0k * w1.y;
            acc[0][6] += a0k * w1.z; acc[0][7] += a0k * w1.w;
            acc[1][0] += a1k * w0.x; acc[1][1] += a1k * w0.y;
            acc[1][2] += a1k * w0.z; acc[1][3] += a1k * w0.w;
            acc[1][4] += a1k * w1.x; acc[1][5] += a1k * w1.y;
            acc[1][6] += a1k * w1.z; acc[1][7] += a1k * w1.w;
        }
    }

    #pragma unroll
    for (int i = 0; i < 2; ++i) {
        int gr = row0 + r0 + i;
        if (gr < n) {
            float4 v0 = make_float4(acc[i][0], acc[i][1], acc[i][2], acc[i][3]);
            float4 v1 = make_float4(acc[i][4], acc[i][5], acc[i][6], acc[i][7]);
            *(float4*)&tout[gr * 64 + tx * 8]     = v0;
            *(float4*)&tout[gr * 64 + tx * 8 + 4] = v1;
        }
    }
}

// -------- aggregate: hout[n] = relu(inv_deg[n] * sum_{e in CSR(n)} t[src_e] + b) --------
__global__ void k_agg(const float* __restrict__ tin, const float* __restrict__ b,
                      float* __restrict__ hout, int n) {
    int node = blockIdx.x * 4 + (threadIdx.x >> 6);
    int d = threadIdx.x & 63;
    if (node >= n) return;
    int s0 = g_offs[node], s1 = g_offs[node + 1];
    float acc = 0.f;
    int e = s0;
    for (; e + 1 < s1; e += 2) {
        int sa = g_srcs[e];
        int sb = g_srcs[e + 1];
        acc += tin[sa * 64 + d];
        acc += tin[sb * 64 + d];
    }
    if (e < s1) acc += tin[g_srcs[e] * 64 + d];
    float o = acc * g_invdeg[node] + b[d];
    hout[node * 64 + d] = fmaxf(o, 0.f);
}

// -------- per-graph mean pool: run-accumulation over sorted graph_ids --------
__global__ void k_pool(const float* __restrict__ h, const int* __restrict__ gid,
                       int n, int nstrips) {
    int strip = blockIdx.x;
    int d = threadIdx.x;                       // 64 threads
    int len = (n + nstrips - 1) / nstrips;
    int lo = strip * len;
    int hi = min(n, lo + len);
    if (lo >= hi) return;
    int cur = gid[lo];
    float acc = 0.f, c = 0.f;
    for (int i = lo; i < hi; ++i) {
        int g = gid[i];
        if (g != cur) {
            atomicAdd(&g_pool[cur * 64 + d], acc);
            if (d == 0) atomicAdd(&g_cnt[cur], c);
            acc = 0.f; c = 0.f; cur = g;
        }
        acc += h[i * 64 + d];
        c += 1.f;
    }
    atomicAdd(&g_pool[cur * 64 + d], acc);
    if (d == 0) atomicAdd(&g_cnt[cur], c);
}

// -------- classifier head: out = (pool/cnt) @ Wc + bc --------
__global__ void k_classify(const float* __restrict__ Wc, const float* __restrict__ bc,
                           float* __restrict__ out, int C) {
    int g = blockIdx.x;
    int c = threadIdx.x;
    if (c >= C) return;
    float icnt = 1.f / fmaxf(g_cnt[g], 1.f);
    float s = 0.f;
    #pragma unroll 8
    for (int d = 0; d < 64; ++d) s += g_pool[g * 64 + d] * Wc[d * C + c];
    out[g * C + c] = s * icnt + bc[c];
}

extern "C" void kernel_launch(void* const* d_in, const int* in_sizes, int n_in,
                              void* d_out, int out_size) {
    const int*   tokens   = (const int*)d_in[0];
    const int*   edge_src = (const int*)d_in[1];
    const int*   edge_dst = (const int*)d_in[2];
    const int*   graph_id = (const int*)d_in[3];
    const float* emb      = (const float*)d_in[4];
    const float* W1       = (const float*)d_in[5];
    const float* b1       = (const float*)d_in[6];
    const float* W2       = (const float*)d_in[7];
    const float* b2       = (const float*)d_in[8];
    const float* Wc       = (const float*)d_in[9];
    const float* bc       = (const float*)d_in[10];
    float* out = (float*)d_out;

    int N = in_sizes[0];
    int E = in_sizes[1];
    int C = in_sizes[10];
    int G = out_size / C;

    float *h0, *h1, *tb;
    cudaGetSymbolAddress((void**)&h0, g_h0);
    cudaGetSymbolAddress((void**)&h1, g_h1);
    cudaGetSymbolAddress((void**)&tb, g_t);

    // 1. init
    k_zero<<<(N + 255) / 256, 256>>>(N, G);
    // 2. degree + inv_deg
    k_deg<<<(E + 255) / 256, 256>>>(edge_dst, E);
    k_invdeg<<<(N + 255) / 256, 256>>>(N);
    // 3. scan -> CSR offsets
    k_scan_a<<<NB_SCAN, 256>>>(N);
    k_scan_b<<<1, 32>>>();
    k_scan_c<<<NB_SCAN, 256>>>(N, E);
    // 4. scatter edges
    k_scatter<<<(E + 255) / 256, 256>>>(edge_src, edge_dst, E);
    // 5. embedding
    k_embed<<<(N * 16 + 255) / 256, 256>>>(tokens, emb, N);
    // 6. layer 1: t = h0 @ W1 ; h1 = relu(agg(t)*inv_deg + b1)
    k_gemm<<<(N + 63) / 64, 256>>>(h0, W1, tb, N);
    k_agg<<<(N + 3) / 4, 256>>>(tb, b1, h1, N);
    // 7. layer 2: t = h1 @ W2 ; h0 = relu(agg(t)*inv_deg + b2)
    k_gemm<<<(N + 63) / 64, 256>>>(h1, W2, tb, N);
    k_agg<<<(N + 3) / 4, 256>>>(tb, b2, h0, N);
    // 8. graph mean pool
    k_pool<<<2048, 64>>>(h0, graph_id, N, 2048);
    // 9. classifier head
    k_classify<<<G, 32>>>(Wc, bc, out, C);
}

// round 2
// speedup vs baseline: 1.5750x; 1.5750x over previous
#include <cuda_runtime.h>
#include <cuda_bf16.h>

#define DD 64
#define NMAX 100000
#define EMAX 1600000
#define NB_SCAN 240

// -------- scratch (static device globals; no allocation) --------
__device__ float g_h0[NMAX * DD];
__device__ float g_h1[NMAX * DD];
__device__ float g_t [NMAX * DD];
__device__ int   g_deg[NMAX];
__device__ int   g_offs[NMAX + 1];
__device__ int   g_cursor[NMAX];
__device__ int   g_srcs[EMAX];
__device__ float g_invdeg[NMAX];
__device__ int   g_bsum[NB_SCAN];
__device__ int   g_boff[NB_SCAN];

// -------- zero degree --------
__global__ void k_zero(int n) {
    int i = blockIdx.x * blockDim.x + threadIdx.x;
    if (i < n) g_deg[i] = 0;
}

// -------- degree count (RED, no return) --------
__global__ void k_deg(const int* __restrict__ dst, int e) {
    int i = blockIdx.x * blockDim.x + threadIdx.x;
    if (i < e) atomicAdd(&g_deg[dst[i]], 1);
}

// -------- scan phase A: per-block sums --------
__global__ void k_scan_a(int n) {
    __shared__ int s[256];
    int b = blockIdx.x;
    int ch = (n + NB_SCAN - 1) / NB_SCAN;
    int lo = b * ch, hi = min(n, lo + ch);
    int t = threadIdx.x;
    int acc = 0;
    for (int i = lo + t; i < hi; i += 256) acc += g_deg[i];
    s[t] = acc;
    __syncthreads();
    for (int off = 128; off > 0; off >>= 1) {
        if (t < off) s[t] += s[t + off];
        __syncthreads();
    }
    if (t == 0) g_bsum[b] = s[0];
}

// -------- scan phase B: scan the 240 block sums (parallel) --------
__global__ void k_scan_b() {
    __shared__ int s[256];
    int t = threadIdx.x;
    int v = (t < NB_SCAN) ? g_bsum[t] : 0;
    s[t] = v;
    __syncthreads();
    for (int off = 1; off < 256; off <<= 1) {
        int x = (t >= off) ? s[t - off] : 0;
        __syncthreads();
        s[t] += x;
        __syncthreads();
    }
    if (t < NB_SCAN) g_boff[t] = s[t] - v;   // exclusive
}

// -------- scan phase C: offsets + cursor + inv_deg --------
__global__ void k_scan_c(int n, int e) {
    __shared__ int s[256];
    int b = blockIdx.x;
    int t = threadIdx.x;
    if (b == 0 && t == 0) g_offs[n] = e;
    int ch = (n + NB_SCAN - 1) / NB_SCAN;
    int lo = b * ch, hi = min(n, lo + ch);
    int carry = g_boff[b];
    for (int base = lo; base < hi; base += 256) {
        int idx = base + t;
        int v = (idx < hi) ? g_deg[idx] : 0;
        s[t] = v;
        __syncthreads();
        for (int off = 1; off < 256; off <<= 1) {
            int x = (t >= off) ? s[t - off] : 0;
            __syncthreads();
            s[t] += x;
            __syncthreads();
        }
        if (idx < hi) {
            int exc = carry + s[t] - v;
            g_offs[idx]   = exc;
            g_cursor[idx] = exc;
            g_invdeg[idx] = 1.0f / (float)(v > 0 ? v : 1);
        }
        carry += s[255];
        __syncthreads();
    }
}

// -------- scatter edges into CSR --------
__global__ void k_scatter(const int* __restrict__ src, const int* __restrict__ dst, int e) {
    int i = blockIdx.x * blockDim.x + threadIdx.x;
    if (i < e) {
        int p = atomicAdd(&g_cursor[dst[i]], 1);
        g_srcs[p] = src[i];
    }
}

// -------- GEMM: t = A @ W, A = hin rows or emb[tok[row]] (fused embedding) --------
// 64-row tile, 128 threads, 4x8 register blocking. FMA-bound.
__global__ void k_gemm(const float* __restrict__ hin, const int* __restrict__ tok,
                       const float* __restrict__ emb, const float* __restrict__ W,
                       float* __restrict__ tout, int n) {
    __shared__ float sA[64 * 66];   // stride 66: conflict-free float2 reads
    __shared__ float sW[64 * 64];
    int t = threadIdx.x;            // 128
    int row0 = blockIdx.x * 64;

    #pragma unroll
    for (int it = 0; it < 8; ++it) {
        int flat = t + it * 128;        // 0..1023 float4 slots
        int r  = flat >> 4;
        int c4 = flat & 15;
        int gr = row0 + r;
        float4 v = make_float4(0.f, 0.f, 0.f, 0.f);
        if (gr < n) {
            if (tok) {
                int token = tok[gr];
                v = ((const float4*)emb)[token * 16 + c4];
            } else {
                v = ((const float4*)hin)[gr * 16 + c4];
            }
        }
        float* p = &sA[r * 66 + c4 * 4];
        *(float2*)p       = make_float2(v.x, v.y);
        *(float2*)(p + 2) = make_float2(v.z, v.w);
        ((float4*)sW)[flat] = ((const float4*)W)[flat];
    }
    __syncthreads();

    int tx = t & 7;            // 8 col groups of 8
    int ty = t >> 3;           // 16 row groups of 4
    int r0 = ty * 4;
    float acc[4][8];
    #pragma unroll
    for (int i = 0; i < 4; ++i)
        #pragma unroll
        for (int j = 0; j < 8; ++j) acc[i][j] = 0.f;

    #pragma unroll
    for (int k4 = 0; k4 < 64; k4 += 4) {
        float a[4][4];
        #pragma unroll
        for (int i = 0; i < 4; ++i) {
            float2 p0 = *(const float2*)&sA[(r0 + i) * 66 + k4];
            float2 p1 = *(const float2*)&sA[(r0 + i) * 66 + k4 + 2];
            a[i][0] = p0.x; a[i][1] = p0.y; a[i][2] = p1.x; a[i][3] = p1.y;
        }
        #pragma unroll
        for (int kk = 0; kk < 4; ++kk) {
            float4 w0 = *(const float4*)&sW[(k4 + kk) * 64 + tx * 8];
            float4 w1 = *(const float4*)&sW[(k4 + kk) * 64 + tx * 8 + 4];
            #pragma unroll
            for (int i = 0; i < 4; ++i) {
                float av = a[i][kk];
                acc[i][0] += av * w0.x; acc[i][1] += av * w0.y;
                acc[i][2] += av * w0.z; acc[i][3] += av * w0.w;
                acc[i][4] += av * w1.x; acc[i][5] += av * w1.y;
                acc[i][6] += av * w1.z; acc[i][7] += av * w1.w;
            }
        }
    }

    #pragma unroll
    for (int i = 0; i < 4; ++i) {
        int gr = row0 + r0 + i;
        if (gr < n) {
            *(float4*)&tout[gr * 64 + tx * 8] =
                make_float4(acc[i][0], acc[i][1], acc[i][2], acc[i][3]);
            *(float4*)&tout[gr * 64 + tx * 8 + 4] =
                make_float4(acc[i][4], acc[i][5], acc[i][6], acc[i][7]);
        }
    }
}

// -------- aggregate: hout[n] = relu(inv_deg[n]*sum_{CSR(n)} t[src] + b) --------
// 16 threads/node, float4 per thread, 4-edge unroll for MLP.
__global__ void k_agg(const float* __restrict__ tin, const float* __restrict__ b,
                      float* __restrict__ hout, int n) {
    int node = blockIdx.x * 16 + (threadIdx.x >> 4);
    int d4 = threadIdx.x & 15;
    if (node >= n) return;
    int s0 = g_offs[node], s1 = g_offs[node + 1];
    const float4* t4 = (const float4*)tin;
    float4 acc = make_float4(0.f, 0.f, 0.f, 0.f);
    int e = s0;
    for (; e + 4 <= s1; e += 4) {
        int sa = g_srcs[e],     sb = g_srcs[e + 1];
        int sc = g_srcs[e + 2], sd = g_srcs[e + 3];
        float4 va = t4[sa * 16 + d4];
        float4 vb = t4[sb * 16 + d4];
        float4 vc = t4[sc * 16 + d4];
        float4 vd = t4[sd * 16 + d4];
        acc.x += (va.x + vb.x) + (vc.x + vd.x);
        acc.y += (va.y + vb.y) + (vc.y + vd.y);
        acc.z += (va.z + vb.z) + (vc.z + vd.z);
        acc.w += (va.w + vb.w) + (vc.w + vd.w);
    }
    for (; e < s1; ++e) {
        float4 v = t4[g_srcs[e] * 16 + d4];
        acc.x += v.x; acc.y += v.y; acc.z += v.z; acc.w += v.w;
    }
    float id = g_invdeg[node];
    float4 bb = ((const float4*)b)[d4];
    float4 o;
    o.x = fmaxf(acc.x * id + bb.x, 0.f);
    o.y = fmaxf(acc.y * id + bb.y, 0.f);
    o.z = fmaxf(acc.z * id + bb.z, 0.f);
    o.w = fmaxf(acc.w * id + bb.w, 0.f);
    ((float4*)hout)[node * 16 + d4] = o;
}

// -------- fused mean-pool + classifier: one block per graph --------
__global__ void k_poolclass(const float* __restrict__ h, const int* __restrict__ gid,
                            const float* __restrict__ Wc, const float* __restrict__ bc,
                            float* __restrict__ out, int n, int C) {
    int g = blockIdx.x;
    __shared__ int sLo, sHi;
    if (threadIdx.x == 0) {
        int lo = 0, hi = n;
        while (lo < hi) { int m = (lo + hi) >> 1; if (gid[m] < g) lo = m + 1; else hi = m; }
        sLo = lo;
        int lo2 = lo, hi2 = n;
        while (lo2 < hi2) { int m = (lo2 + hi2) >> 1; if (gid[m] < g + 1) lo2 = m + 1; else hi2 = m; }
        sHi = lo2;
    }
    __syncthreads();
    int lo = sLo, hi = sHi;
    int d  = threadIdx.x & 63;
    int rg = threadIdx.x >> 6;               // 0..7 (512 threads)
    float acc = 0.f;
    for (int i = lo + rg; i < hi; i += 8) acc += h[i * 64 + d];
    __shared__ float sm[512];
    __shared__ float mean[64];
    sm[threadIdx.x] = acc;
    __syncthreads();
    if (threadIdx.x < 64) {
        float s = 0.f;
        #pragma unroll
        for (int k = 0; k < 8; ++k) s += sm[k * 64 + d];
        float cnt = (float)(hi - lo);
        mean[d] = s / fmaxf(cnt, 1.f);
    }
    __syncthreads();
    if ((int)threadIdx.x < C) {
        int c = threadIdx.x;
        float s = 0.f;
        #pragma unroll
        for (int dd = 0; dd < 64; ++dd) s += mean[dd] * Wc[dd * C + c];
        out[g * C + c] = s + bc[c];
    }
}

extern "C" void kernel_launch(void* const* d_in, const int* in_sizes, int n_in,
                              void* d_out, int out_size) {
    const int*   tokens   = (const int*)d_in[0];
    const int*   edge_src = (const int*)d_in[1];
    const int*   edge_dst = (const int*)d_in[2];
    const int*   graph_id = (const int*)d_in[3];
    const float* emb      = (const float*)d_in[4];
    const float* W1       = (const float*)d_in[5];
    const float* b1       = (const float*)d_in[6];
    const float* W2       = (const float*)d_in[7];
    const float* b2       = (const float*)d_in[8];
    const float* Wc       = (const float*)d_in[9];
    const float* bc       = (const float*)d_in[10];
    float* out = (float*)d_out;

    int N = in_sizes[0];
    int E = in_sizes[1];
    int C = in_sizes[10];
    int G = out_size / C;

    float *h0, *h1, *tb;
    cudaGetSymbolAddress((void**)&h0, g_h0);
    cudaGetSymbolAddress((void**)&h1, g_h1);
    cudaGetSymbolAddress((void**)&tb, g_t);

    // CSR build
    k_zero<<<(N + 255) / 256, 256>>>(N);
    k_deg<<<(E + 255) / 256, 256>>>(edge_dst, E);
    k_scan_a<<<NB_SCAN, 256>>>(N);
    k_scan_b<<<1, 256>>>();
    k_scan_c<<<NB_SCAN, 256>>>(N, E);
    k_scatter<<<(E + 255) / 256, 256>>>(edge_src, edge_dst, E);

    // layer 1: t = emb[tokens] @ W1 (fused embedding); h1 = relu(agg(t)*invdeg + b1)
    k_gemm<<<(N + 63) / 64, 128>>>(nullptr, tokens, emb, W1, tb, N);
    k_agg <<<(N + 15) / 16, 256>>>(tb, b1, h1, N);

    // layer 2
    k_gemm<<<(N + 63) / 64, 128>>>(h1, nullptr, nullptr, W2, tb, N);
    k_agg <<<(N + 15) / 16, 256>>>(tb, b2, h0, N);

    // fused pool + classify
    k_poolclass<<<G, 512>>>(h0, graph_id, Wc, bc, out, N, C);
}

// round 3
// speedup vs baseline: 1.6990x; 1.0787x over previous
#include <cuda_runtime.h>
#include <cuda_fp16.h>

#define DD 64
#define NMAX 100000
#define EMAX 1600000
#define NB_SCAN 240

// -------- scratch (static device globals; zero-initialized at load) --------
__device__ float  g_h0[NMAX * DD];
__device__ float  g_h1[NMAX * DD];
__device__ __half g_th[NMAX * DD];     // half-precision t = h @ W
__device__ int    g_deg[NMAX];         // must be 0 at entry; restored by k_agg(reset)
__device__ int    g_offs[NMAX + 1];
__device__ int    g_cursor[NMAX];
__device__ int    g_srcs[EMAX];
__device__ float  g_invdeg[NMAX];
__device__ int    g_bsum[NB_SCAN];

// -------- degree count: 4 edges/thread, int4 loads --------
__global__ void k_deg(const int* __restrict__ dst, int e) {
    int i = blockIdx.x * blockDim.x + threadIdx.x;
    int base = i * 4;
    if (base + 4 <= e) {
        int4 d = *(const int4*)(dst + base);
        atomicAdd(&g_deg[d.x], 1);
        atomicAdd(&g_deg[d.y], 1);
        atomicAdd(&g_deg[d.z], 1);
        atomicAdd(&g_deg[d.w], 1);
    } else {
        for (int j = base; j < e; ++j) atomicAdd(&g_deg[dst[j]], 1);
    }
}

// -------- scan phase A: per-block sums --------
__global__ void k_scan_a(int n) {
    __shared__ int s[256];
    int b = blockIdx.x;
    int ch = (n + NB_SCAN - 1) / NB_SCAN;
    int lo = b * ch, hi = min(n, lo + ch);
    int t = threadIdx.x;
    int acc = 0;
    for (int i = lo + t; i < hi; i += 256) acc += g_deg[i];
    s[t] = acc;
    __syncthreads();
    for (int off = 128; off > 0; off >>= 1) {
        if (t < off) s[t] += s[t + off];
        __syncthreads();
    }
    if (t == 0) g_bsum[b] = s[0];
}

// -------- scan phase C: each block computes its own carry, then local scan --------
__global__ void k_scan_c(int n, int e) {
    __shared__ int s[256];
    __shared__ int sCarry;
    int b = blockIdx.x;
    int t = threadIdx.x;
    if (b == 0 && t == 0) g_offs[n] = e;

    // inline "scan_b": reduce block sums [0, b)
    int partial = (t < b) ? g_bsum[t] : 0;    // b <= NB_SCAN <= 256
    s[t] = partial;
    __syncthreads();
    for (int off = 128; off > 0; off >>= 1) {
        if (t < off) s[t] += s[t + off];
        __syncthreads();
    }
    if (t == 0) sCarry = s[0];
    __syncthreads();
    int carry = sCarry;
    __syncthreads();

    int ch = (n + NB_SCAN - 1) / NB_SCAN;
    int lo = b * ch, hi = min(n, lo + ch);
    for (int base = lo; base < hi; base += 256) {
        int idx = base + t;
        int v = (idx < hi) ? g_deg[idx] : 0;
        s[t] = v;
        __syncthreads();
        for (int off = 1; off < 256; off <<= 1) {
            int x = (t >= off) ? s[t - off] : 0;
            __syncthreads();
            s[t] += x;
            __syncthreads();
        }
        if (idx < hi) {
            int exc = carry + s[t] - v;
            g_offs[idx]   = exc;
            g_cursor[idx] = exc;
            g_invdeg[idx] = 1.0f / (float)(v > 0 ? v : 1);
        }
        carry += s[255];
        __syncthreads();
    }
}

// -------- scatter edges into CSR: 4 edges/thread --------
__global__ void k_scatter(const int* __restrict__ src, const int* __restrict__ dst, int e) {
    int i = blockIdx.x * blockDim.x + threadIdx.x;
    int base = i * 4;
    if (base + 4 <= e) {
        int4 sv = *(const int4*)(src + base);
        int4 dv = *(const int4*)(dst + base);
        g_srcs[atomicAdd(&g_cursor[dv.x], 1)] = sv.x;
        g_srcs[atomicAdd(&g_cursor[dv.y], 1)] = sv.y;
        g_srcs[atomicAdd(&g_cursor[dv.z], 1)] = sv.z;
        g_srcs[atomicAdd(&g_cursor[dv.w], 1)] = sv.w;
    } else {
        for (int j = base; j < e; ++j)
            g_srcs[atomicAdd(&g_cursor[dst[j]], 1)] = src[j];
    }
}

// -------- GEMM: t(half) = A @ W, A = hin rows or emb[tok[row]] --------
// 64-row tile, 128 threads, 4x8 register blocking.
__global__ void k_gemm(const float* __restrict__ hin, const int* __restrict__ tok,
                       const float* __restrict__ emb, const float* __restrict__ W,
                       __half* __restrict__ tout, int n) {
    __shared__ float sA[64 * 66];   // stride 66: conflict-free float2 reads
    __shared__ float sW[64 * 64];
    int t = threadIdx.x;            // 128
    int row0 = blockIdx.x * 64;

    #pragma unroll
    for (int it = 0; it < 8; ++it) {
        int flat = t + it * 128;        // 0..1023 float4 slots
        int r  = flat >> 4;
        int c4 = flat & 15;
        int gr = row0 + r;
        float4 v = make_float4(0.f, 0.f, 0.f, 0.f);
        if (gr < n) {
            if (tok) {
                int token = tok[gr];
                v = ((const float4*)emb)[token * 16 + c4];
            } else {
                v = ((const float4*)hin)[gr * 16 + c4];
            }
        }
        float* p = &sA[r * 66 + c4 * 4];
        *(float2*)p       = make_float2(v.x, v.y);
        *(float2*)(p + 2) = make_float2(v.z, v.w);
        ((float4*)sW)[flat] = ((const float4*)W)[flat];
    }
    __syncthreads();

    int tx = t & 7;            // 8 col groups of 8
    int ty = t >> 3;           // 16 row groups of 4
    int r0 = ty * 4;
    float acc[4][8];
    #pragma unroll
    for (int i = 0; i < 4; ++i)
        #pragma unroll
        for (int j = 0; j < 8; ++j) acc[i][j] = 0.f;

    #pragma unroll
    for (int k4 = 0; k4 < 64; k4 += 4) {
        float a[4][4];
        #pragma unroll
        for (int i = 0; i < 4; ++i) {
            float2 p0 = *(const float2*)&sA[(r0 + i) * 66 + k4];
            float2 p1 = *(const float2*)&sA[(r0 + i) * 66 + k4 + 2];
            a[i][0] = p0.x; a[i][1] = p0.y; a[i][2] = p1.x; a[i][3] = p1.y;
        }
        #pragma unroll
        for (int kk = 0; kk < 4; ++kk) {
            float4 w0 = *(const float4*)&sW[(k4 + kk) * 64 + tx * 8];
            float4 w1 = *(const float4*)&sW[(k4 + kk) * 64 + tx * 8 + 4];
            #pragma unroll
            for (int i = 0; i < 4; ++i) {
                float av = a[i][kk];
                acc[i][0] += av * w0.x; acc[i][1] += av * w0.y;
                acc[i][2] += av * w0.z; acc[i][3] += av * w0.w;
                acc[i][4] += av * w1.x; acc[i][5] += av * w1.y;
                acc[i][6] += av * w1.z; acc[i][7] += av * w1.w;
            }
        }
    }

    // convert 8 floats -> 8 halves (one uint4) per row, store
    #pragma unroll
    for (int i = 0; i < 4; ++i) {
        int gr = row0 + r0 + i;
        if (gr < n) {
            __half2 h0 = __floats2half2_rn(acc[i][0], acc[i][1]);
            __half2 h1 = __floats2half2_rn(acc[i][2], acc[i][3]);
            __half2 h2 = __floats2half2_rn(acc[i][4], acc[i][5]);
            __half2 h3 = __floats2half2_rn(acc[i][6], acc[i][7]);
            uint4 pk;
            pk.x = *(unsigned*)&h0; pk.y = *(unsigned*)&h1;
            pk.z = *(unsigned*)&h2; pk.w = *(unsigned*)&h3;
            ((uint4*)tout)[gr * 8 + tx] = pk;
        }
    }
}

// -------- aggregate: hout = relu(invdeg * sum_{CSR} t_half[src] + b) --------
// 8 threads/node, each handles 8 half features (16B uint4 per edge).
__global__ void k_agg(const __half* __restrict__ tin, const float* __restrict__ b,
                      float* __restrict__ hout, int n, int resetDeg) {
    int node = blockIdx.x * 32 + (threadIdx.x >> 3);
    int d8 = threadIdx.x & 7;
    if (node >= n) return;
    int s0 = g_offs[node], s1 = g_offs[node + 1];
    const uint4* t4 = (const uint4*)tin;

    float2 acc0 = make_float2(0.f, 0.f), acc1 = acc0, acc2 = acc0, acc3 = acc0;
    int e = s0;
    for (; e + 4 <= s1; e += 4) {
        int sa = g_srcs[e],     sb = g_srcs[e + 1];
        int sc = g_srcs[e + 2], sd = g_srcs[e + 3];
        uint4 va = t4[sa * 8 + d8];
        uint4 vb = t4[sb * 8 + d8];
        uint4 vc = t4[sc * 8 + d8];
        uint4 vd = t4[sd * 8 + d8];
        #pragma unroll
        for (int q = 0; q < 4; ++q) {
            unsigned ua = (&va.x)[q], ub = (&vb.x)[q], uc = (&vc.x)[q], ud = (&vd.x)[q];
            float2 fa = __half22float2(*(__half2*)&ua);
            float2 fb = __half22float2(*(__half2*)&ub);
            float2 fc = __half22float2(*(__half2*)&uc);
            float2 fd = __half22float2(*(__half2*)&ud);
            float2* a = (q == 0) ? &acc0 : (q == 1) ? &acc1 : (q == 2) ? &acc2 : &acc3;
            a->x += (fa.x + fb.x) + (fc.x + fd.x);
            a->y += (fa.y + fb.y) + (fc.y + fd.y);
        }
    }
    for (; e < s1; ++e) {
        uint4 v = t4[g_srcs[e] * 8 + d8];
        #pragma unroll
        for (int q = 0; q < 4; ++q) {
            unsigned u = (&v.x)[q];
            float2 f = __half22float2(*(__half2*)&u);
            float2* a = (q == 0) ? &acc0 : (q == 1) ? &acc1 : (q == 2) ? &acc2 : &acc3;
            a->x += f.x; a->y += f.y;
        }
    }

    float id = g_invdeg[node];
    float4 b0 = ((const float4*)b)[d8 * 2];
    float4 b1 = ((const float4*)b)[d8 * 2 + 1];
    float4 o0, o1;
    o0.x = fmaxf(acc0.x * id + b0.x, 0.f);
    o0.y = fmaxf(acc0.y * id + b0.y, 0.f);
    o0.z = fmaxf(acc1.x * id + b0.z, 0.f);
    o0.w = fmaxf(acc1.y * id + b0.w, 0.f);
    o1.x = fmaxf(acc2.x * id + b1.x, 0.f);
    o1.y = fmaxf(acc2.y * id + b1.y, 0.f);
    o1.z = fmaxf(acc3.x * id + b1.z, 0.f);
    o1.w = fmaxf(acc3.y * id + b1.w, 0.f);
    ((float4*)hout)[node * 16 + d8 * 2]     = o0;
    ((float4*)hout)[node * 16 + d8 * 2 + 1] = o1;

    if (resetDeg && d8 == 0) g_deg[node] = 0;   // restore invariant for next launch
}

// -------- fused mean-pool + classifier: one block per graph --------
__global__ void k_poolclass(const float* __restrict__ h, const int* __restrict__ gid,
                            const float* __restrict__ Wc, const float* __restrict__ bc,
                            float* __restrict__ out, int n, int C) {
    int g = blockIdx.x;
    __shared__ int sLo, sHi;
    if (threadIdx.x == 0) {
        int lo = 0, hi = n;
        while (lo < hi) { int m = (lo + hi) >> 1; if (gid[m] < g) lo = m + 1; else hi = m; }
        sLo = lo;
        int lo2 = lo, hi2 = n;
        while (lo2 < hi2) { int m = (lo2 + hi2) >> 1; if (gid[m] < g + 1) lo2 = m + 1; else hi2 = m; }
        sHi = lo2;
    }
    __syncthreads();
    int lo = sLo, hi = sHi;
    int d  = threadIdx.x & 63;
    int rg = threadIdx.x >> 6;               // 0..7 (512 threads)
    float acc = 0.f;
    for (int i = lo + rg; i < hi; i += 8) acc += h[i * 64 + d];
    __shared__ float sm[512];
    __shared__ float mean[64];
    sm[threadIdx.x] = acc;
    __syncthreads();
    if (threadIdx.x < 64) {
        float s = 0.f;
        #pragma unroll
        for (int k = 0; k < 8; ++k) s += sm[k * 64 + d];
        float cnt = (float)(hi - lo);
        mean[d] = s / fmaxf(cnt, 1.f);
    }
    __syncthreads();
    if ((int)threadIdx.x < C) {
        int c = threadIdx.x;
        float s = 0.f;
        #pragma unroll
        for (int dd = 0; dd < 64; ++dd) s += mean[dd] * Wc[dd * C + c];
        out[g * C + c] = s + bc[c];
    }
}

extern "C" void kernel_launch(void* const* d_in, const int* in_sizes, int n_in,
                              void* d_out, int out_size) {
    const int*   tokens   = (const int*)d_in[0];
    const int*   edge_src = (const int*)d_in[1];
    const int*   edge_dst = (const int*)d_in[2];
    const int*   graph_id = (const int*)d_in[3];
    const float* emb      = (const float*)d_in[4];
    const float* W1       = (const float*)d_in[5];
    const float* b1       = (const float*)d_in[6];
    const float* W2       = (const float*)d_in[7];
    const float* b2       = (const float*)d_in[8];
    const float* Wc       = (const float*)d_in[9];
    const float* bc       = (const float*)d_in[10];
    float* out = (float*)d_out;

    int N = in_sizes[0];
    int E = in_sizes[1];
    int C = in_sizes[10];
    int G = out_size / C;

    float  *h0, *h1;
    __half *tb;
    cudaGetSymbolAddress((void**)&h0, g_h0);
    cudaGetSymbolAddress((void**)&h1, g_h1);
    cudaGetSymbolAddress((void**)&tb, g_th);

    int e4 = (E + 3) / 4;

    // CSR build (g_deg guaranteed zero: init at load, reset by agg-1 each launch)
    k_deg    <<<(e4 + 255) / 256, 256>>>(edge_dst, E);
    k_scan_a <<<NB_SCAN, 256>>>(N);
    k_scan_c <<<NB_SCAN, 256>>>(N, E);
    k_scatter<<<(e4 + 255) / 256, 256>>>(edge_src, edge_dst, E);

    // layer 1: t = emb[tokens] @ W1 ; h1 = relu(agg(t)*invdeg + b1) ; reset deg
    k_gemm<<<(N + 63) / 64, 128>>>(nullptr, tokens, emb, W1, tb, N);
    k_agg <<<(N + 31) / 32, 256>>>(tb, b1, h1, N, 1);

    // layer 2
    k_gemm<<<(N + 63) / 64, 128>>>(h1, nullptr, nullptr, W2, tb, N);
    k_agg <<<(N + 31) / 32, 256>>>(tb, b2, h0, N, 0);

    // fused pool + classify
    k_poolclass<<<G, 512>>>(h0, graph_id, Wc, bc, out, N, C);
}